// round 2
// baseline (speedup 1.0000x reference)
#include <cuda_runtime.h>
#include <math.h>

// ---------------------------------------------------------------------------
// Problem:
//   inp [16,1,64,64,64] -> block0 (gated) -> [16,20,33,33,33] (stored padded 39^3)
//                       -> block1 (gated) -> [16,20,18,18,18]
//                       -> block2 (none)  -> mean -> [16,20] -> fc -> [16,2]
// Block2+mean collapsed: mean(conv2(x)) = (1/1000) * S[b,ci,t] . K2[co,ci,t]
// Conv mainloops use packed fma.rn.f32x2 (2 FMA/instr).
// ---------------------------------------------------------------------------

#define PD0 39   // 33 + 2*3 halo

__device__ float g_B[3*125];
__device__ float g_K0[1*125*24];
__device__ float g_K1[20*125*24];
__device__ float g_K2[20*125*20];
__device__ float g_act0[16*20*PD0*PD0*PD0];   // zero-initialized -> halo stays 0
__device__ float g_act1[16*20*18*18*18];
__device__ float g_S[16*20*125];

// ---------------------------------------------------------------------------
__global__ void k_basis(float* __restrict__ B) {
    __shared__ double vals[3][125];
    int t = threadIdx.x;
    if (t < 125) {
        int dz = t / 25 - 2, dy = (t / 5) % 5 - 2, dx = t % 5 - 2;
        double r = sqrt((double)(dz*dz + dy*dy + dx*dx));
        for (int j = 0; j < 3; j++) {
            double d = (r - (double)j) / 0.6;
            vals[j][t] = exp(-0.5 * d * d);
        }
    }
    __syncthreads();
    if (t < 3) {
        double s = 0.0;
        for (int i = 0; i < 125; i++) s += vals[t][i] * vals[t][i];
        double inv = 1.0 / sqrt(s);
        for (int i = 0; i < 125; i++) B[t*125 + i] = (float)(vals[t][i] * inv);
    }
}

__global__ void k_synth(const float* __restrict__ W, const float* __restrict__ B,
                        float* __restrict__ K, int CIN, int COUTC, int CP) {
    int idx = blockIdx.x * blockDim.x + threadIdx.x;
    int total = CIN * 125 * CP;
    if (idx >= total) return;
    int co = idx % CP;
    int t  = (idx / CP) % 125;
    int ci = idx / (CP * 125);
    float v = 0.f;
    if (co < COUTC) {
        for (int j = 0; j < 3; j++)
            v += W[(co*CIN + ci)*3 + j] * B[j*125 + t];
    }
    K[idx] = v;
}

// ---------------------------------------------------------------------------
// Packed f32x2 helpers
// ---------------------------------------------------------------------------
__device__ __forceinline__ unsigned long long bcast_f32x2(float x) {
    unsigned long long r;
    unsigned int xi = __float_as_uint(x);
    asm("mov.b64 %0, {%1, %1};" : "=l"(r) : "r"(xi));
    return r;
}
__device__ __forceinline__ void fma_f32x2(unsigned long long& d,
                                          unsigned long long a,
                                          unsigned long long b) {
    asm("fma.rn.f32x2 %0, %1, %2, %0;" : "+l"(d) : "l"(a), "l"(b));
}
__device__ __forceinline__ float2 unpack_f32x2(unsigned long long v) {
    unsigned int lo, hi;
    asm("mov.b64 {%0, %1}, %2;" : "=r"(lo), "=r"(hi) : "l"(v));
    return make_float2(__uint_as_float(lo), __uint_as_float(hi));
}

// ---------------------------------------------------------------------------
// Gated stride-2 size-5 conv3d, register-row-blocked, f32x2-packed channels.
//  PADDED: input tensor has a built-in 3-halo (dims DIN+6), no bounds checks.
//  OUTPAD: output written into a 3-halo padded layout of dim DOUT+6.
// ---------------------------------------------------------------------------
template<int CIN, int COUTC, int CP, int C, int P,
         int TZ, int TY, int TX, int DIN, int DOUT,
         bool PADDED, bool OUTPAD, int OCC>
__global__ void __launch_bounds__((TZ*TY)*(TX/P)*(CP/C), OCC)
conv_gated_kernel(const float* __restrict__ in, const float* __restrict__ Kw,
                  float* __restrict__ out)
{
    constexpr int XC   = TX / P;
    constexpr int ROWS = TZ * TY;
    constexpr int CG   = CP / C;
    constexpr int NT   = ROWS * XC * CG;
    constexpr int IZ = 2*TZ + 3, IY = 2*TY + 3, IX = 2*TX + 3;
    constexpr int IN_ELEMS = IZ * IY * IX;
    constexpr int IN_PAD   = (IN_ELEMS + 3) & ~3;
    constexpr int NPT = TZ * TY * TX;
    constexpr int TYC = (DOUT + TY - 1) / TY;
    constexpr int C2  = C / 2;
    constexpr int DINP = PADDED ? DIN + 6 : DIN;
    constexpr int DO_P = OUTPAD ? DOUT + 6 : DOUT;

    extern __shared__ float smem[];
    float* sIn = smem;            // [IN_PAD]
    float* sW  = smem + IN_PAD;   // [125*CP]
    float* sY  = smem;            // [NPT*CP] (aliases; used after mainloop)

    const int tid   = threadIdx.x;
    const int b     = blockIdx.y;
    const int tilez = blockIdx.x / TYC;
    const int tiley = blockIdx.x % TYC;
    const int oz0 = tilez * TZ, oy0 = tiley * TY;

    const int cg  = tid / (ROWS * XC);
    const int rem = tid % (ROWS * XC);
    const int row = rem / XC;
    const int xc  = rem % XC;
    const int rz = row / TY, ry = row % TY;
    const bool valid = (oz0 + rz < DOUT) && (oy0 + ry < DOUT);
    const int xbase = xc * P;

    unsigned long long acc[P][C2];
#pragma unroll
    for (int p = 0; p < P; p++)
#pragma unroll
        for (int c = 0; c < C2; c++) acc[p][c] = 0ull;

    for (int ci = 0; ci < CIN; ci++) {
        // ---- cooperative input-tile load ----
        const float* gin = in + (long)(b*CIN + ci) * (DINP*(long)DINP*DINP);
        for (int idx = tid; idx < IN_ELEMS; idx += NT) {
            int iz = idx / (IY*IX);
            int r2 = idx % (IY*IX);
            int iy = r2 / IX;
            int ix = r2 % IX;
            float v;
            if (PADDED) {
                v = gin[((2*oz0 + iz)*DINP + (2*oy0 + iy))*DINP + ix];
            } else {
                int gz = 2*oz0 - 3 + iz;
                int gy = 2*oy0 - 3 + iy;
                int gx = ix - 3;
                v = 0.f;
                if ((unsigned)gz < (unsigned)DIN && (unsigned)gy < (unsigned)DIN &&
                    (unsigned)gx < (unsigned)DIN)
                    v = gin[(gz*DIN + gy)*DIN + gx];
            }
            sIn[idx] = v;
        }
        // ---- cooperative weight load [125][CP] ----
        const float* gw = Kw + ci * 125 * CP;
        for (int idx = tid; idx < 125*CP; idx += NT) sW[idx] = gw[idx];
        __syncthreads();

        if (valid) {
            for (int tz = 0; tz < 5; tz++) {
#pragma unroll
                for (int ty = 0; ty < 5; ty++) {
                    float rowv[2*P + 3];
                    const float* rp =
                        &sIn[((2*rz + tz)*IY + (2*ry + ty))*IX + 2*xbase];
#pragma unroll
                    for (int k = 0; k < 2*P + 3; k++) rowv[k] = rp[k];
#pragma unroll
                    for (int tx = 0; tx < 5; tx++) {
                        unsigned long long wv[C2];
                        const unsigned long long* wp =
                            reinterpret_cast<const unsigned long long*>(
                                &sW[(tz*25 + ty*5 + tx)*CP + cg*C]);
#pragma unroll
                        for (int c = 0; c < C2; c++) wv[c] = wp[c];
#pragma unroll
                        for (int p = 0; p < P; p++) {
                            unsigned long long x2 = bcast_f32x2(rowv[2*p + tx]);
#pragma unroll
                            for (int c = 0; c < C2; c++)
                                fma_f32x2(acc[p][c], x2, wv[c]);
                        }
                    }
                }
            }
        }
        __syncthreads();
    }

    // ---- epilogue: stage conv outputs, gate, write 20 channels ----
    if (valid) {
#pragma unroll
        for (int p = 0; p < P; p++)
#pragma unroll
            for (int c = 0; c < C2; c++) {
                float2 f = unpack_f32x2(acc[p][c]);
                sY[(row*TX + xbase + p)*CP + cg*C + 2*c    ] = f.x;
                sY[(row*TX + xbase + p)*CP + cg*C + 2*c + 1] = f.y;
            }
    }
    __syncthreads();

    for (int idx = tid; idx < NPT*3; idx += NT) {
        int pt = idx % NPT;
        int k  = idx / NPT;
        int rr = pt / TX;
        int rzz = rr / TY, ryy = rr % TY;
        if (oz0 + rzz < DOUT && oy0 + ryy < DOUT) {
            float g = sY[pt*CP + 20 + k];
            sY[pt*CP + 20 + k] = 1.f / (1.f + expf(-g));
        }
    }
    __syncthreads();

    float* gout = out + (long)b * 20 * (DO_P*(long)DO_P*DO_P);
    for (int idx = tid; idx < NPT*20; idx += NT) {
        int pt = idx % NPT;
        int oc = idx / NPT;
        int ox  = pt % TX;
        int rr  = pt / TX;
        int ryy = rr % TY;
        int rzz = rr / TY;
        int oz = oz0 + rzz, oy = oy0 + ryy;
        if (oz < DOUT && oy < DOUT && ox < DOUT) {
            float y = sY[pt*CP + oc];
            float v;
            if (oc < 5) {
                v = fmaxf(y, 0.f);
            } else {
                int gi = (oc < 8) ? 0 : ((oc < 13) ? 1 : 2);
                v = y * sY[pt*CP + 20 + gi];
            }
            if (OUTPAD)
                gout[((long)oc*DO_P + (oz+3))*(DO_P*DO_P) + (oy+3)*DO_P + (ox+3)] = v;
            else
                gout[((long)oc*DO_P + oz)*(DO_P*DO_P) + oy*DO_P + ox] = v;
        }
    }
}

// ---------------------------------------------------------------------------
// S[b,ci,t] = sum over 10^3 stride-2 sampled points of act1 (pad 3) per tap t.
// ---------------------------------------------------------------------------
__global__ void kS_kernel(const float* __restrict__ act, float* __restrict__ S) {
    __shared__ float s[5832];
    int ci = blockIdx.x;
    int b  = blockIdx.y;
    int tid = threadIdx.x;
    const float* p = act + (long)(b*20 + ci) * 5832;
    for (int i = tid; i < 5832; i += 128) s[i] = p[i];
    __syncthreads();
    if (tid < 125) {
        int tz = tid / 25, ty = (tid / 5) % 5, tx = tid % 5;
        float sum = 0.f;
        for (int oz = 0; oz < 10; oz++) {
            int z = 2*oz + tz - 3;
            if ((unsigned)z >= 18u) continue;
            for (int oy = 0; oy < 10; oy++) {
                int y = 2*oy + ty - 3;
                if ((unsigned)y >= 18u) continue;
                int base = (z*18 + y)*18;
                for (int ox = 0; ox < 10; ox++) {
                    int x = 2*ox + tx - 3;
                    if ((unsigned)x >= 18u) continue;
                    sum += s[base + x];
                }
            }
        }
        S[(b*20 + ci)*125 + tid] = sum;
    }
}

// ---------------------------------------------------------------------------
__global__ void head_kernel(const float* __restrict__ S, const float* __restrict__ K2,
                            const float* __restrict__ fc1w, const float* __restrict__ fc1b,
                            const float* __restrict__ fc2w, const float* __restrict__ fc2b,
                            float* __restrict__ out) {
    __shared__ float pooled[16*20];
    __shared__ float h1[16*50];
    int t = threadIdx.x;  // 320 threads
    {
        int b  = t / 20;
        int co = t % 20;
        float a0 = 0.f, a1 = 0.f;
        const float* sp = S + b*2500;
        for (int i = 0; i < 2500; i += 2) {
            a0 = fmaf(sp[i    ], K2[(i    )*20 + co], a0);
            a1 = fmaf(sp[i + 1], K2[(i + 1)*20 + co], a1);
        }
        pooled[b*20 + co] = (a0 + a1) * (1.0f/1000.0f);
    }
    __syncthreads();
    for (int idx = t; idx < 16*50; idx += 320) {
        int b = idx / 50, j = idx % 50;
        float a = fc1b[j];
        for (int k = 0; k < 20; k++)
            a = fmaf(pooled[b*20 + k], fc1w[j*20 + k], a);
        h1[b*50 + j] = fmaxf(a, 0.f);
    }
    __syncthreads();
    if (t < 32) {
        int b = t / 2, o = t % 2;
        float a = fc2b[o];
        for (int k = 0; k < 50; k++)
            a = fmaf(h1[b*50 + k], fc2w[o*50 + k], a);
        out[b*2 + o] = a;
    }
}

// ---------------------------------------------------------------------------
extern "C" void kernel_launch(void* const* d_in, const int* in_sizes, int n_in,
                              void* d_out, int out_size) {
    const float* inp  = (const float*)d_in[0];
    const float* W0   = (const float*)d_in[1];
    const float* W1   = (const float*)d_in[2];
    const float* W2   = (const float*)d_in[3];
    const float* fc1w = (const float*)d_in[4];
    const float* fc1b = (const float*)d_in[5];
    const float* fc2w = (const float*)d_in[6];
    const float* fc2b = (const float*)d_in[7];
    float* out = (float*)d_out;

    float *gB, *gK0, *gK1, *gK2, *gA0, *gA1, *gS;
    cudaGetSymbolAddress((void**)&gB,  g_B);
    cudaGetSymbolAddress((void**)&gK0, g_K0);
    cudaGetSymbolAddress((void**)&gK1, g_K1);
    cudaGetSymbolAddress((void**)&gK2, g_K2);
    cudaGetSymbolAddress((void**)&gA0, g_act0);
    cudaGetSymbolAddress((void**)&gA1, g_act1);
    cudaGetSymbolAddress((void**)&gS,  g_S);

    k_basis<<<1, 128>>>(gB);
    k_synth<<<(1*125*24 + 255)/256,  256>>>(W0, gB, gK0, 1, 23, 24);
    k_synth<<<(20*125*24 + 255)/256, 256>>>(W1, gB, gK1, 20, 23, 24);
    k_synth<<<(20*125*20 + 255)/256, 256>>>(W2, gB, gK2, 20, 20, 20);

    // ---- conv0: [16,1,64^3] -> gated [16,20,39^3 padded] ----
    // tile (6,3,33), P=3 -> XC=11, CG=2, NT=396
    {
        constexpr int IN_PAD = ((15*9*69) + 3) & ~3;       // 9316
        constexpr int YF = (6*3*33)*24;                    // 14256
        constexpr int SMEM = (YF > IN_PAD + 125*24 ? YF : IN_PAD + 125*24) * 4;
        auto k = conv_gated_kernel<1, 23, 24, 12, 3, 6, 3, 33, 64, 33,
                                   false, true, 1>;
        cudaFuncSetAttribute(k, cudaFuncAttributeMaxDynamicSharedMemorySize, SMEM);
        k<<<dim3(6*11, 16), 396, SMEM>>>(inp, gK0, gA0);
    }

    // ---- conv1: [16,20,39^3 padded] -> gated [16,20,18^3] ----
    // tile (6,3,18), P=3 -> XC=6, CG=2, NT=216, 2 CTAs/SM
    {
        constexpr int IN_PAD = ((15*9*39) + 3) & ~3;       // 5268
        constexpr int YF = (6*3*18)*24;                    // 7776
        constexpr int SMEM = (YF > IN_PAD + 125*24 ? YF : IN_PAD + 125*24) * 4;
        auto k = conv_gated_kernel<20, 23, 24, 12, 3, 6, 3, 18, 33, 18,
                                   true, false, 2>;
        cudaFuncSetAttribute(k, cudaFuncAttributeMaxDynamicSharedMemorySize, SMEM);
        k<<<dim3(3*6, 16), 216, SMEM>>>(gA0, gK1, gA1);
    }

    // ---- block2 collapsed ----
    kS_kernel<<<dim3(20, 16), 128>>>(gA1, gS);
    head_kernel<<<1, 320>>>(gS, gK2, fc1w, fc1b, fc2w, fc2b, out);
}

// round 3
// speedup vs baseline: 2.2476x; 2.2476x over previous
#include <cuda_runtime.h>
#include <math.h>

// ---------------------------------------------------------------------------
// Factorized radial-basis CNN.
//   K[o,i,tap] = sum_j W[o,i,j] * B[j,tap], B radial with 10 distinct values
//   (orbits by r^2 in {0,1,2,3,4,5,6,8,9,12}).
//   y[o] = sum_{i,j} W[o,i,j] * U[i,j],  U[i,j] = sum_g B[j,g] * T[i,g],
//   T[i,g] = orbit-sum of shifted inputs.  ~7x fewer pipe ops than direct conv.
// Pipeline:
//   conv0: [16,1,64^3] -> gated [16,20,39^3 padded(+3 halo, zeros)]
//   conv1: padded -> gated [16,20,18^3]
//   kS:    tap sums S[b,ci,125] of act1 (block2+mean collapsed)
//   head:  fold B+W2 into pooled dot, fc1(relu), fc2
// ---------------------------------------------------------------------------

#define PD0 39

__device__ float g_act0[16*20*PD0*PD0*PD0];   // zero-init => halo stays 0
__device__ float g_act1[16*20*18*18*18];
__device__ float g_S[16*20*125];

struct BC { float b[30]; };   // [j*10 + orbit]

__host__ __device__ constexpr int orbit_of(int tz, int ty, int tx) {
    int dz = tz - 2, dy = ty - 2, dx = tx - 2;
    int r2 = dz*dz + dy*dy + dx*dx;            // in {0..6, 8, 9, 12}
    return r2 <= 6 ? r2 : (r2 == 8 ? 7 : (r2 == 9 ? 8 : 9));
}

// ---------------------------------------------------------------------------
// conv0: CIN=1, DIN=64, DOUT=33. Tile (3,3,33), P=3, NT=99. Output padded.
// ---------------------------------------------------------------------------
__global__ void __launch_bounds__(99)
conv0_kernel(const float* __restrict__ in, const float* __restrict__ W,
             float* __restrict__ out, BC Bc)
{
    constexpr int NT = 99, IY = 9, IX = 69;     // IZ=9
    __shared__ float sIn[9*9*69 + 3];           // 5589
    __shared__ float sW[72];                    // [j][o24]
    __shared__ float sB[32];

    const int tid = threadIdx.x;
    const int b   = blockIdx.y;
    const int zt  = blockIdx.x / 11, yt = blockIdx.x % 11;
    const int oz0 = 3*zt, oy0 = 3*yt;

    if (tid < 72) {
        int j = tid / 24, o = tid % 24;
        sW[tid] = (o < 23) ? W[o*3 + j] : 0.f;
    }
    if (tid < 30) sB[tid] = Bc.b[tid];

    const float* gin = in + (long)b * (64*64*64);
    for (int idx = tid; idx < 9*9*69; idx += NT) {
        int iz = idx / (IY*IX), r = idx % (IY*IX), iy = r / IX, ix = r % IX;
        int gz = 2*oz0 - 3 + iz, gy = 2*oy0 - 3 + iy, gx = ix - 3;
        float v = 0.f;
        if ((unsigned)gz < 64u && (unsigned)gy < 64u && (unsigned)gx < 64u)
            v = gin[(gz*64 + gy)*64 + gx];
        sIn[idx] = v;
    }
    __syncthreads();

    const int row = tid / 11;            // 0..8
    const int xc  = tid % 11;
    const int rz = row / 3, ry = row % 3;
    const int xbase = xc * 3;

    float T[3][10];
#pragma unroll
    for (int p = 0; p < 3; p++)
#pragma unroll
        for (int g = 0; g < 10; g++) T[p][g] = 0.f;

#pragma unroll
    for (int tz = 0; tz < 5; tz++)
#pragma unroll
    for (int ty = 0; ty < 5; ty++) {
        const float* rp = &sIn[(2*rz + tz)*(IY*IX) + (2*ry + ty)*IX + 2*xbase];
        float rowv[9];
#pragma unroll
        for (int k = 0; k < 9; k++) rowv[k] = rp[k];
#pragma unroll
        for (int tx = 0; tx < 5; tx++) {
            const int g = orbit_of(tz, ty, tx);
            T[0][g] += rowv[tx];
            T[1][g] += rowv[tx + 2];
            T[2][g] += rowv[tx + 4];
        }
    }

    float U[3][3] = {};
#pragma unroll
    for (int j = 0; j < 3; j++)
#pragma unroll
    for (int g = 0; g < 10; g++) {
        float bv = sB[j*10 + g];
        U[0][j] = fmaf(bv, T[0][g], U[0][j]);
        U[1][j] = fmaf(bv, T[1][g], U[1][j]);
        U[2][j] = fmaf(bv, T[2][g], U[2][j]);
    }

    const float4* w4 = (const float4*)sW;
    const int oz = oz0 + rz, oy = oy0 + ry;
    float* gout = out + (long)b * 20 * (PD0*PD0*PD0);
#pragma unroll
    for (int p = 0; p < 3; p++) {
        float y[24];
#pragma unroll
        for (int c = 0; c < 24; c++) y[c] = 0.f;
#pragma unroll
        for (int j = 0; j < 3; j++)
#pragma unroll
        for (int q = 0; q < 6; q++) {
            float4 w = w4[j*6 + q];
            y[q*4+0] = fmaf(U[p][j], w.x, y[q*4+0]);
            y[q*4+1] = fmaf(U[p][j], w.y, y[q*4+1]);
            y[q*4+2] = fmaf(U[p][j], w.z, y[q*4+2]);
            y[q*4+3] = fmaf(U[p][j], w.w, y[q*4+3]);
        }
        int ox = xbase + p;
        float g0 = 1.f/(1.f + expf(-y[20]));
        float g1 = 1.f/(1.f + expf(-y[21]));
        float g2 = 1.f/(1.f + expf(-y[22]));
#pragma unroll
        for (int oc = 0; oc < 20; oc++) {
            float v = (oc < 5) ? fmaxf(y[oc], 0.f)
                               : y[oc] * (oc < 8 ? g0 : (oc < 13 ? g1 : g2));
            gout[((long)oc*PD0 + (oz+3))*(PD0*PD0) + (oy+3)*PD0 + (ox+3)] = v;
        }
    }
}

// ---------------------------------------------------------------------------
// conv1: CIN=20, padded input (39^3), DOUT=18. Tile (2,6,18), P=2, NT=108.
// ---------------------------------------------------------------------------
__global__ void __launch_bounds__(108)
conv1_kernel(const float* __restrict__ in, const float* __restrict__ W,
             float* __restrict__ out, BC Bc)
{
    constexpr int NT = 108;
    __shared__ float sIn[4096];         // 7 z-slices * 585 (=15*39)
    __shared__ float sW[20*3*24];       // [ci][j][o24]
    __shared__ float sB[32];

    const int tid = threadIdx.x;
    const int b   = blockIdx.y;
    const int zt  = blockIdx.x / 3, yt = blockIdx.x % 3;
    const int oz0 = 2*zt, oy0 = 6*yt;

    for (int idx = tid; idx < 1440; idx += NT) {
        int ci = idx / 72, r = idx % 72, j = r / 24, o = r % 24;
        sW[idx] = (o < 23) ? W[(o*20 + ci)*3 + j] : 0.f;
    }
    if (tid < 30) sB[tid] = Bc.b[tid];

    const int row = tid / 9;            // 0..11
    const int xc  = tid % 9;
    const int rz = row / 6, ry = row % 6;
    const int xbase = xc * 2;

    float acc[2][24];
#pragma unroll
    for (int p = 0; p < 2; p++)
#pragma unroll
        for (int c = 0; c < 24; c++) acc[p][c] = 0.f;

    for (int ci = 0; ci < 20; ci++) {
        // tile rows are contiguous: 7 z-slices of 15*39=585 contiguous floats
        const float* gin = in + (long)(b*20 + ci)*(PD0*PD0*PD0)
                              + (2*oz0)*(PD0*PD0) + (2*oy0)*PD0;
#pragma unroll
        for (int iz = 0; iz < 7; iz++) {
            const float* src = gin + iz*(PD0*PD0);
            for (int k = tid; k < 585; k += NT) sIn[iz*585 + k] = src[k];
        }
        __syncthreads();

        float T[2][10];
#pragma unroll
        for (int p = 0; p < 2; p++)
#pragma unroll
            for (int g = 0; g < 10; g++) T[p][g] = 0.f;

#pragma unroll
        for (int tz = 0; tz < 5; tz++)
#pragma unroll
        for (int ty = 0; ty < 5; ty++) {
            const float* rp = &sIn[(2*rz + tz)*585 + (2*ry + ty)*39 + 2*xbase];
            float rowv[7];
#pragma unroll
            for (int k = 0; k < 7; k++) rowv[k] = rp[k];
#pragma unroll
            for (int tx = 0; tx < 5; tx++) {
                const int g = orbit_of(tz, ty, tx);
                T[0][g] += rowv[tx];
                T[1][g] += rowv[tx + 2];
            }
        }

        float U[2][3] = {};
#pragma unroll
        for (int j = 0; j < 3; j++)
#pragma unroll
        for (int g = 0; g < 10; g++) {
            float bv = sB[j*10 + g];
            U[0][j] = fmaf(bv, T[0][g], U[0][j]);
            U[1][j] = fmaf(bv, T[1][g], U[1][j]);
        }

        const float4* w4 = (const float4*)&sW[ci*72];
#pragma unroll
        for (int j = 0; j < 3; j++)
#pragma unroll
        for (int q = 0; q < 6; q++) {
            float4 w = w4[j*6 + q];
#pragma unroll
            for (int p = 0; p < 2; p++) {
                acc[p][q*4+0] = fmaf(U[p][j], w.x, acc[p][q*4+0]);
                acc[p][q*4+1] = fmaf(U[p][j], w.y, acc[p][q*4+1]);
                acc[p][q*4+2] = fmaf(U[p][j], w.z, acc[p][q*4+2]);
                acc[p][q*4+3] = fmaf(U[p][j], w.w, acc[p][q*4+3]);
            }
        }
        __syncthreads();
    }

    const int oz = oz0 + rz, oy = oy0 + ry;
    float* gout = out + (long)b * 20 * 5832;
#pragma unroll
    for (int p = 0; p < 2; p++) {
        int ox = xbase + p;
        float g0 = 1.f/(1.f + expf(-acc[p][20]));
        float g1 = 1.f/(1.f + expf(-acc[p][21]));
        float g2 = 1.f/(1.f + expf(-acc[p][22]));
#pragma unroll
        for (int oc = 0; oc < 20; oc++) {
            float y = acc[p][oc];
            float v = (oc < 5) ? fmaxf(y, 0.f)
                               : y * (oc < 8 ? g0 : (oc < 13 ? g1 : g2));
            gout[((long)oc*18 + oz)*324 + oy*18 + ox] = v;
        }
    }
}

// ---------------------------------------------------------------------------
// S[b,ci,t] = sum over 10^3 stride-2 sampled (pad 3) points of act1, per tap.
// ---------------------------------------------------------------------------
__global__ void kS_kernel(const float* __restrict__ act, float* __restrict__ S) {
    __shared__ float s[5832];
    int ci = blockIdx.x;
    int b  = blockIdx.y;
    int tid = threadIdx.x;
    const float* p = act + (long)(b*20 + ci) * 5832;
    for (int i = tid; i < 5832; i += 128) s[i] = p[i];
    __syncthreads();
    if (tid < 125) {
        int tz = tid / 25, ty = (tid / 5) % 5, tx = tid % 5;
        float sum = 0.f;
        for (int oz = 0; oz < 10; oz++) {
            int z = 2*oz + tz - 3;
            if ((unsigned)z >= 18u) continue;
            for (int oy = 0; oy < 10; oy++) {
                int y = 2*oy + ty - 3;
                if ((unsigned)y >= 18u) continue;
                int base = (z*18 + y)*18;
                for (int ox = 0; ox < 10; ox++) {
                    int x = 2*ox + tx - 3;
                    if ((unsigned)x >= 18u) continue;
                    sum += s[base + x];
                }
            }
        }
        S[(b*20 + ci)*125 + tid] = sum;
    }
}

// ---------------------------------------------------------------------------
// head: V[b,ci,j] = sum_t B[j,t]*S[b,ci,t];
//       pooled[b,o] = (1/1000) sum_{ci,j} W2[o,ci,j]*V[b,ci,j]; fc1(relu); fc2
// ---------------------------------------------------------------------------
__global__ void head_kernel(const float* __restrict__ S, const float* __restrict__ W2,
                            const float* __restrict__ fc1w, const float* __restrict__ fc1b,
                            const float* __restrict__ fc2w, const float* __restrict__ fc2b,
                            float* __restrict__ out, BC Bc)
{
    __shared__ float V[960];       // [b][ci][j]
    __shared__ float pooled[320];
    __shared__ float h1[800];
    int t = threadIdx.x;           // 320
    for (int idx = t; idx < 960; idx += 320) {
        int b = idx / 60, r = idx % 60, ci = r / 3, j = r % 3;
        const float* sp = S + (b*20 + ci)*125;
        float sum = 0.f;
#pragma unroll
        for (int tz = 0; tz < 5; tz++)
#pragma unroll
        for (int ty = 0; ty < 5; ty++)
#pragma unroll
        for (int tx = 0; tx < 5; tx++)
            sum = fmaf(Bc.b[j*10 + orbit_of(tz,ty,tx)], sp[(tz*5+ty)*5 + tx], sum);
        V[idx] = sum;
    }
    __syncthreads();
    {
        int b = t / 20, o = t % 20;
        float a = 0.f;
        for (int ci = 0; ci < 20; ci++)
#pragma unroll
            for (int j = 0; j < 3; j++)
                a = fmaf(W2[(o*20 + ci)*3 + j], V[(b*20 + ci)*3 + j], a);
        pooled[t] = a * (1.0f/1000.0f);
    }
    __syncthreads();
    for (int idx = t; idx < 16*50; idx += 320) {
        int b = idx / 50, j = idx % 50;
        float a = fc1b[j];
        for (int k = 0; k < 20; k++)
            a = fmaf(pooled[b*20 + k], fc1w[j*20 + k], a);
        h1[b*50 + j] = fmaxf(a, 0.f);
    }
    __syncthreads();
    if (t < 32) {
        int b = t / 2, o = t % 2;
        float a = fc2b[o];
        for (int k = 0; k < 50; k++)
            a = fmaf(h1[b*50 + k], fc2w[o*50 + k], a);
        out[b*2 + o] = a;
    }
}

// ---------------------------------------------------------------------------
extern "C" void kernel_launch(void* const* d_in, const int* in_sizes, int n_in,
                              void* d_out, int out_size) {
    const float* inp  = (const float*)d_in[0];
    const float* W0   = (const float*)d_in[1];
    const float* W1   = (const float*)d_in[2];
    const float* W2   = (const float*)d_in[3];
    const float* fc1w = (const float*)d_in[4];
    const float* fc1b = (const float*)d_in[5];
    const float* fc2w = (const float*)d_in[6];
    const float* fc2b = (const float*)d_in[7];
    float* out = (float*)d_out;

    // host-side radial basis (deterministic, double precision, sfcnn norm)
    BC bc;
    {
        const double r2s[10]  = {0,1,2,3,4,5,6,8,9,12};
        const double mult[10] = {1,6,12,8,6,24,24,12,24,8};
        for (int j = 0; j < 3; j++) {
            double v[10], s = 0.0;
            for (int g = 0; g < 10; g++) {
                double d = (sqrt(r2s[g]) - (double)j) / 0.6;
                v[g] = exp(-0.5 * d * d);
                s += mult[g] * v[g] * v[g];
            }
            double inv = 1.0 / sqrt(s);
            for (int g = 0; g < 10; g++) bc.b[j*10 + g] = (float)(v[g] * inv);
        }
    }

    float *gA0, *gA1, *gS;
    cudaGetSymbolAddress((void**)&gA0, g_act0);
    cudaGetSymbolAddress((void**)&gA1, g_act1);
    cudaGetSymbolAddress((void**)&gS,  g_S);

    conv0_kernel<<<dim3(11*11, 16),  99>>>(inp, W0, gA0, bc);
    conv1_kernel<<<dim3(9*3,  16), 108>>>(gA0, W1, gA1, bc);
    kS_kernel<<<dim3(20, 16), 128>>>(gA1, gS);
    head_kernel<<<1, 320>>>(gS, W2, fc1w, fc1b, fc2w, fc2b, out, bc);
}

// round 5
// speedup vs baseline: 4.0688x; 1.8103x over previous
#include <cuda_runtime.h>
#include <math.h>

// ---------------------------------------------------------------------------
// Factorized radial-basis CNN (see R3). R5 = R4 with the conv1 cp.async
// stride bug fixed (smem slabs are 40-stride; the fill now writes 40-stride).
// ---------------------------------------------------------------------------

#define PD0 39

__device__ float g_act0[16*20*PD0*PD0*PD0];   // zero-init => halo stays 0
__device__ float g_act1[16*20*18*18*18];
__device__ float g_V[16*20*3];

struct BC { float b[30]; };   // [j*10 + orbit]

__host__ __device__ constexpr int orbit_of(int tz, int ty, int tx) {
    int dz = tz - 2, dy = ty - 2, dx = tx - 2;
    int r2 = dz*dz + dy*dy + dx*dx;            // {0..6, 8, 9, 12}
    return r2 <= 6 ? r2 : (r2 == 8 ? 7 : (r2 == 9 ? 8 : 9));
}

__device__ __forceinline__ void cp_async4(float* dst, const float* src) {
    unsigned int d = (unsigned int)__cvta_generic_to_shared(dst);
    asm volatile("cp.async.ca.shared.global [%0], [%1], 4;" :: "r"(d), "l"(src));
}

// ---------------------------------------------------------------------------
// conv0: CIN=1, 64^3 -> 33^3 (padded out 39^3). Tile (3z,3y,33x), P=3 along z.
// threads: ox = tid%33, oy = tid/33  (99 threads; lanes -> consecutive ox)
// ---------------------------------------------------------------------------
__global__ void __launch_bounds__(99)
conv0_kernel(const float* __restrict__ in, const float* __restrict__ W,
             float* __restrict__ out, BC Bc)
{
    __shared__ float sIn[9*9*70];     // z 9, y 9, x 70 (pad for float2 align)
    __shared__ float sW[72];          // [j][o24]
    __shared__ float sB[32];

    const int tid = threadIdx.x;
    const int b   = blockIdx.y;
    const int zt  = blockIdx.x / 11, yt = blockIdx.x % 11;
    const int oz0 = 3*zt, oy0 = 3*yt;

    if (tid < 72) { int j = tid/24, o = tid%24; sW[tid] = (o < 23) ? W[o*3 + j] : 0.f; }
    if (tid < 30) sB[tid] = Bc.b[tid];

    const float* gin = in + (long)b * (64*64*64);
    for (int idx = tid; idx < 9*9*70; idx += 99) {
        int iz = idx / 630, r = idx % 630, iy = r / 70, ix = r % 70;
        int gz = 2*oz0 - 3 + iz, gy = 2*oy0 - 3 + iy, gx = ix - 3;
        float v = 0.f;
        if (ix < 69 && (unsigned)gz < 64u && (unsigned)gy < 64u && (unsigned)gx < 64u)
            v = gin[(gz*64 + gy)*64 + gx];
        sIn[idx] = v;
    }
    __syncthreads();

    const int ox = tid % 33;
    const int oy = tid / 33;     // 0..2

    float T[3][10];
#pragma unroll
    for (int p = 0; p < 3; p++)
#pragma unroll
        for (int g = 0; g < 10; g++) T[p][g] = 0.f;

#pragma unroll
    for (int s = 0; s < 9; s++) {
#pragma unroll
        for (int ty = 0; ty < 5; ty++) {
            const float2* rp = (const float2*)&sIn[(s*9 + (2*oy + ty))*70 + 2*ox];
            float2 c0 = rp[0], c1 = rp[1], c2 = rp[2];
            float v0 = c0.x, v1 = c0.y, v2 = c1.x, v3 = c1.y, v4 = c2.x;
#pragma unroll
            for (int p = 0; p < 3; p++) {
                const int tz = s - 2*p;
                if (tz >= 0 && tz <= 4) {      // compile-time resolved
                    T[p][orbit_of(tz, ty, 0)] += v0;
                    T[p][orbit_of(tz, ty, 1)] += v1;
                    T[p][orbit_of(tz, ty, 2)] += v2;
                    T[p][orbit_of(tz, ty, 3)] += v3;
                    T[p][orbit_of(tz, ty, 4)] += v4;
                }
            }
        }
    }

    float U[3][3] = {};
#pragma unroll
    for (int j = 0; j < 3; j++)
#pragma unroll
    for (int g = 0; g < 10; g++) {
        float bv = sB[j*10 + g];
        U[0][j] = fmaf(bv, T[0][g], U[0][j]);
        U[1][j] = fmaf(bv, T[1][g], U[1][j]);
        U[2][j] = fmaf(bv, T[2][g], U[2][j]);
    }

    const float4* w4 = (const float4*)sW;
    float* gout = out + (long)b * 20 * (PD0*PD0*PD0);
#pragma unroll
    for (int p = 0; p < 3; p++) {
        float y[24];
#pragma unroll
        for (int c = 0; c < 24; c++) y[c] = 0.f;
#pragma unroll
        for (int j = 0; j < 3; j++)
#pragma unroll
        for (int q = 0; q < 6; q++) {
            float4 w = w4[j*6 + q];
            y[q*4+0] = fmaf(U[p][j], w.x, y[q*4+0]);
            y[q*4+1] = fmaf(U[p][j], w.y, y[q*4+1]);
            y[q*4+2] = fmaf(U[p][j], w.z, y[q*4+2]);
            y[q*4+3] = fmaf(U[p][j], w.w, y[q*4+3]);
        }
        const int oz = oz0 + p;
        float g0 = 1.f/(1.f + expf(-y[20]));
        float g1 = 1.f/(1.f + expf(-y[21]));
        float g2 = 1.f/(1.f + expf(-y[22]));
#pragma unroll
        for (int oc = 0; oc < 20; oc++) {
            float v = (oc < 5) ? fmaxf(y[oc], 0.f)
                               : y[oc] * (oc < 8 ? g0 : (oc < 13 ? g1 : g2));
            gout[((long)oc*PD0 + (oz+3))*(PD0*PD0) + (oy0+oy+3)*PD0 + (ox+3)] = v;
        }
    }
}

// ---------------------------------------------------------------------------
// conv1: CIN=20, padded 39^3 -> 18^3. Tile (6z,6y,18x), 324 threads.
//   thread: ox=tid%18, q=tid/18: zq=q/6 (0..2), oy=q%6; owns p=0,1 (oz=2zq+p)
//   cp.async double-buffered over ci. smem: 15 z-slabs, 15 rows of 40 each.
// ---------------------------------------------------------------------------
__global__ void __launch_bounds__(324, 1)
conv1_kernel(const float* __restrict__ in, const float* __restrict__ W,
             float* __restrict__ out, BC Bc)
{
    constexpr int NT = 324, SLAB = 600;      // 15 rows * 40
    extern __shared__ float dsm[];
    float* buf[2] = { dsm, dsm + 9000 };
    float* sW = dsm + 18000;                  // 1440
    float* sB = sW + 1440;                    // 30

    const int tid = threadIdx.x;
    const int b   = blockIdx.y;
    const int zt  = blockIdx.x / 3, yt = blockIdx.x % 3;
    const int oz0 = 6*zt, oy0 = 6*yt;

    for (int idx = tid; idx < 1440; idx += NT) {
        int ci = idx / 72, r = idx % 72, j = r / 24, o = r % 24;
        sW[idx] = (o < 23) ? W[(o*20 + ci)*3 + j] : 0.f;
    }
    if (tid < 30) sB[tid] = Bc.b[tid];

    const int ox = tid % 18;
    const int q  = tid / 18;
    const int zq = q / 6, oy = q % 6;

    float acc[2][24];
#pragma unroll
    for (int p = 0; p < 2; p++)
#pragma unroll
        for (int c = 0; c < 24; c++) acc[p][c] = 0.f;

    // fill: 15 z-slabs, each 15 rows of 39 valid floats, written 40-stride
    auto issue = [&](int ci, float* dst) {
        const float* g = in + (long)(b*20 + ci)*(PD0*PD0*PD0)
                            + (2*oz0)*(PD0*PD0) + (2*oy0)*PD0;
        for (int idx = tid; idx < 15*15*39; idx += NT) {
            int iz = idx / 585, k = idx % 585;
            int row = k / 39, col = k % 39;
            cp_async4(dst + iz*SLAB + row*40 + col,
                      g + iz*(PD0*PD0) + row*PD0 + col);
        }
        asm volatile("cp.async.commit_group;");
    };

    issue(0, buf[0]);
    for (int ci = 0; ci < 20; ci++) {
        float* cur = buf[ci & 1];
        if (ci + 1 < 20) {
            issue(ci + 1, buf[(ci + 1) & 1]);
            asm volatile("cp.async.wait_group 1;");
        } else {
            asm volatile("cp.async.wait_group 0;");
        }
        __syncthreads();

        float T[2][10];
#pragma unroll
        for (int p = 0; p < 2; p++)
#pragma unroll
            for (int g = 0; g < 10; g++) T[p][g] = 0.f;

#pragma unroll
        for (int ss = 0; ss < 7; ss++) {
#pragma unroll
            for (int ty = 0; ty < 5; ty++) {
                const float2* rp = (const float2*)
                    &cur[(4*zq + ss)*SLAB + (2*oy + ty)*40 + 2*ox];
                float2 c0 = rp[0], c1 = rp[1], c2 = rp[2];
                float v0 = c0.x, v1 = c0.y, v2 = c1.x, v3 = c1.y, v4 = c2.x;
#pragma unroll
                for (int p = 0; p < 2; p++) {
                    const int tz = ss - 2*p;
                    if (tz >= 0 && tz <= 4) {
                        T[p][orbit_of(tz, ty, 0)] += v0;
                        T[p][orbit_of(tz, ty, 1)] += v1;
                        T[p][orbit_of(tz, ty, 2)] += v2;
                        T[p][orbit_of(tz, ty, 3)] += v3;
                        T[p][orbit_of(tz, ty, 4)] += v4;
                    }
                }
            }
        }

        float U[2][3] = {};
#pragma unroll
        for (int j = 0; j < 3; j++)
#pragma unroll
        for (int g = 0; g < 10; g++) {
            float bv = sB[j*10 + g];
            U[0][j] = fmaf(bv, T[0][g], U[0][j]);
            U[1][j] = fmaf(bv, T[1][g], U[1][j]);
        }

        const float4* w4 = (const float4*)&sW[ci*72];
#pragma unroll
        for (int j = 0; j < 3; j++)
#pragma unroll
        for (int qq = 0; qq < 6; qq++) {
            float4 w = w4[j*6 + qq];
#pragma unroll
            for (int p = 0; p < 2; p++) {
                acc[p][qq*4+0] = fmaf(U[p][j], w.x, acc[p][qq*4+0]);
                acc[p][qq*4+1] = fmaf(U[p][j], w.y, acc[p][qq*4+1]);
                acc[p][qq*4+2] = fmaf(U[p][j], w.z, acc[p][qq*4+2]);
                acc[p][qq*4+3] = fmaf(U[p][j], w.w, acc[p][qq*4+3]);
            }
        }
        __syncthreads();   // protect buffer reuse
    }

    float* gout = out + (long)b * 20 * 5832;
#pragma unroll
    for (int p = 0; p < 2; p++) {
        const int oz = oz0 + 2*zq + p;
        float g0 = 1.f/(1.f + expf(-acc[p][20]));
        float g1 = 1.f/(1.f + expf(-acc[p][21]));
        float g2 = 1.f/(1.f + expf(-acc[p][22]));
#pragma unroll
        for (int oc = 0; oc < 20; oc++) {
            float y = acc[p][oc];
            float v = (oc < 5) ? fmaxf(y, 0.f)
                               : y * (oc < 8 ? g0 : (oc < 13 ? g1 : g2));
            gout[((long)oc*18 + oz)*324 + (oy0 + oy)*18 + ox] = v;
        }
    }
}

// ---------------------------------------------------------------------------
// kS + fused B-contraction: V[b,ci,j] = sum_t B[j,orbit(t)] * S_t
// ---------------------------------------------------------------------------
__global__ void kS_kernel(const float* __restrict__ act, float* __restrict__ V,
                          BC Bc) {
    __shared__ float s[5832];
    __shared__ float R[1620];     // [z][y][tx]
    __shared__ float sS[128];
    int ci = blockIdx.x;
    int b  = blockIdx.y;
    int tid = threadIdx.x;        // 128
    const float* p = act + (long)(b*20 + ci) * 5832;
    for (int i = tid; i < 5832; i += 128) s[i] = p[i];
    __syncthreads();

    for (int idx = tid; idx < 1620; idx += 128) {
        int z = idx / 90, r = idx % 90, y = r / 5, tx = r % 5;
        int lo = (3 - tx + 1) >> 1; if (lo < 0) lo = 0;
        int hi = (20 - tx) >> 1;    if (hi > 9) hi = 9;
        float sum = 0.f;
        const float* row = &s[(z*18 + y)*18];
        for (int oxx = lo; oxx <= hi; oxx++) sum += row[2*oxx + tx - 3];
        R[idx] = sum;
    }
    __syncthreads();

    if (tid < 125) {
        int tz = tid / 25, ty = (tid / 5) % 5, tx = tid % 5;
        int loz = (3 - tz + 1) >> 1; if (loz < 0) loz = 0;
        int hiz = (20 - tz) >> 1;    if (hiz > 9) hiz = 9;
        int loy = (3 - ty + 1) >> 1; if (loy < 0) loy = 0;
        int hiy = (20 - ty) >> 1;    if (hiy > 9) hiy = 9;
        float sum = 0.f;
        for (int oz = loz; oz <= hiz; oz++) {
            int z = 2*oz + tz - 3;
            for (int oyy = loy; oyy <= hiy; oyy++)
                sum += R[((z)*18 + (2*oyy + ty - 3))*5 + tx];
        }
        sS[tid] = sum;
    }
    __syncthreads();

    if (tid < 3) {
        float a = 0.f;
        for (int t = 0; t < 125; t++) {
            int tz = t / 25, ty = (t / 5) % 5, tx = t % 5;
            a = fmaf(Bc.b[tid*10 + orbit_of(tz, ty, tx)], sS[t], a);
        }
        V[(b*20 + ci)*3 + tid] = a;
    }
}

// ---------------------------------------------------------------------------
__global__ void head_kernel(const float* __restrict__ V, const float* __restrict__ W2,
                            const float* __restrict__ fc1w, const float* __restrict__ fc1b,
                            const float* __restrict__ fc2w, const float* __restrict__ fc2b,
                            float* __restrict__ out)
{
    __shared__ float sV[960];      // [b][ci][j]
    __shared__ float sW2[1380];    // [o][ci][j]
    __shared__ float pooled[320];
    __shared__ float h1[800];
    int t = threadIdx.x;           // 320
    for (int i = t; i < 960;  i += 320) sV[i]  = V[i];
    for (int i = t; i < 1380; i += 320) sW2[i] = W2[i];
    __syncthreads();
    {
        int b = t / 20, o = t % 20;
        float a = 0.f;
        for (int ci = 0; ci < 20; ci++)
#pragma unroll
            for (int j = 0; j < 3; j++)
                a = fmaf(sW2[(o*20 + ci)*3 + j], sV[(b*20 + ci)*3 + j], a);
        pooled[t] = a * (1.0f/1000.0f);
    }
    __syncthreads();
    for (int idx = t; idx < 16*50; idx += 320) {
        int b = idx / 50, j = idx % 50;
        float a = fc1b[j];
        for (int k = 0; k < 20; k++)
            a = fmaf(pooled[b*20 + k], fc1w[j*20 + k], a);
        h1[b*50 + j] = fmaxf(a, 0.f);
    }
    __syncthreads();
    if (t < 32) {
        int b = t / 2, o = t % 2;
        float a = fc2b[o];
        for (int k = 0; k < 50; k++)
            a = fmaf(h1[b*50 + k], fc2w[o*50 + k], a);
        out[b*2 + o] = a;
    }
}

// ---------------------------------------------------------------------------
extern "C" void kernel_launch(void* const* d_in, const int* in_sizes, int n_in,
                              void* d_out, int out_size) {
    const float* inp  = (const float*)d_in[0];
    const float* W0   = (const float*)d_in[1];
    const float* W1   = (const float*)d_in[2];
    const float* W2   = (const float*)d_in[3];
    const float* fc1w = (const float*)d_in[4];
    const float* fc1b = (const float*)d_in[5];
    const float* fc2w = (const float*)d_in[6];
    const float* fc2b = (const float*)d_in[7];
    float* out = (float*)d_out;

    BC bc;
    {
        const double r2s[10]  = {0,1,2,3,4,5,6,8,9,12};
        const double mult[10] = {1,6,12,8,6,24,24,12,24,8};
        for (int j = 0; j < 3; j++) {
            double v[10], sm = 0.0;
            for (int g = 0; g < 10; g++) {
                double d = (sqrt(r2s[g]) - (double)j) / 0.6;
                v[g] = exp(-0.5 * d * d);
                sm += mult[g] * v[g] * v[g];
            }
            double inv = 1.0 / sqrt(sm);
            for (int g = 0; g < 10; g++) bc.b[j*10 + g] = (float)(v[g] * inv);
        }
    }

    float *gA0, *gA1, *gV;
    cudaGetSymbolAddress((void**)&gA0, g_act0);
    cudaGetSymbolAddress((void**)&gA1, g_act1);
    cudaGetSymbolAddress((void**)&gV,  g_V);

    conv0_kernel<<<dim3(11*11, 16), 99>>>(inp, W0, gA0, bc);

    constexpr int SMEM1 = (18000 + 1440 + 32) * 4;   // 77.9 KB
    cudaFuncSetAttribute(conv1_kernel,
                         cudaFuncAttributeMaxDynamicSharedMemorySize, SMEM1);
    conv1_kernel<<<dim3(3*3, 16), 324, SMEM1>>>(gA0, W1, gA1, bc);

    kS_kernel<<<dim3(20, 16), 128>>>(gA1, gV, bc);
    head_kernel<<<1, 320>>>(gV, W2, fc1w, fc1b, fc2w, fc2b, out);
}

// round 6
// speedup vs baseline: 5.7686x; 1.4178x over previous
#include <cuda_runtime.h>
#include <math.h>

// ---------------------------------------------------------------------------
// Factorized radial-basis CNN (see R3/R5). R6:
//  - act0 stored [16,20,39,39,40] (x-stride 40): conv1 smem tile layout ==
//    global layout -> contiguous 16B cp.async copies (3.5 ops/thread).
//  - conv1: 648 threads (1 z-output/thread), 20 warps/SM, double-buffered.
//  - conv0: 297 threads, tile (9z,3y,33x), dynamic smem.
//  - head: one block per batch element.
// ---------------------------------------------------------------------------

#define PZ 39
#define PX 40
#define PLANE (PZ*PZ*PX)      // 60840 floats per (b,ci) act0 plane

__device__ float g_act0[16*20*PLANE];    // zero-init => halo+pad stay 0
__device__ float g_act1[16*20*18*18*18];
__device__ float g_V[16*20*3];

struct BC { float b[30]; };   // [j*10 + orbit]

__host__ __device__ constexpr int orbit_of(int tz, int ty, int tx) {
    int dz = tz - 2, dy = ty - 2, dx = tx - 2;
    int r2 = dz*dz + dy*dy + dx*dx;            // {0..6, 8, 9, 12}
    return r2 <= 6 ? r2 : (r2 == 8 ? 7 : (r2 == 9 ? 8 : 9));
}

__device__ __forceinline__ void cp_async16(float* dst, const float* src) {
    unsigned int d = (unsigned int)__cvta_generic_to_shared(dst);
    asm volatile("cp.async.cg.shared.global [%0], [%1], 16;" :: "r"(d), "l"(src));
}

// ---------------------------------------------------------------------------
// conv0: CIN=1, 64^3 -> 33^3 into padded [39,39,40]. Tile (9z,3y,33x),
// 297 threads; thread: ox=tid%33, oy=(tid/33)%3, zg=tid/99; 3 z-outputs (p).
// ---------------------------------------------------------------------------
__global__ void __launch_bounds__(297)
conv0_kernel(const float* __restrict__ in, const float* __restrict__ W,
             float* __restrict__ out, BC Bc)
{
    extern __shared__ float sm0[];
    float* sIn = sm0;              // 21 z x 9 y x 70 x = 13230
    float* sW  = sm0 + 13232;      // 72, 16B-aligned
    float* sB  = sW + 72;          // 30

    const int tid = threadIdx.x;
    const int b   = blockIdx.y;
    const int zt  = blockIdx.x / 11, yt = blockIdx.x % 11;
    const int oz0 = 9*zt, oy0 = 3*yt;

    if (tid < 72) { int j = tid/24, o = tid%24; sW[tid] = (o < 23) ? W[o*3 + j] : 0.f; }
    if (tid < 30) sB[tid] = Bc.b[tid];

    const float* gin = in + (long)b * (64*64*64);
    for (int idx = tid; idx < 21*9*70; idx += 297) {
        int iz = idx / 630, r = idx % 630, iy = r / 70, ix = r % 70;
        int gz = 2*oz0 - 3 + iz, gy = 2*oy0 - 3 + iy, gx = ix - 3;
        float v = 0.f;
        if (ix < 69 && (unsigned)gz < 64u && (unsigned)gy < 64u && (unsigned)gx < 64u)
            v = gin[(gz*64 + gy)*64 + gx];
        sIn[idx] = v;
    }
    __syncthreads();

    const int ox = tid % 33;
    const int r0 = tid / 33;
    const int oy = r0 % 3;
    const int zg = r0 / 3;         // 0..2; thread's z-outputs: oz0+3*zg+p

    float T[3][10];
#pragma unroll
    for (int p = 0; p < 3; p++)
#pragma unroll
        for (int g = 0; g < 10; g++) T[p][g] = 0.f;

#pragma unroll
    for (int s = 0; s < 9; s++) {          // iz = 6*zg + s ; tz = s - 2p
#pragma unroll
        for (int ty = 0; ty < 5; ty++) {
            const float2* rp = (const float2*)
                &sIn[((6*zg + s)*9 + (2*oy + ty))*70 + 2*ox];
            float2 c0 = rp[0], c1 = rp[1], c2 = rp[2];
            float v0 = c0.x, v1 = c0.y, v2 = c1.x, v3 = c1.y, v4 = c2.x;
#pragma unroll
            for (int p = 0; p < 3; p++) {
                const int tz = s - 2*p;
                if (tz >= 0 && tz <= 4) {
                    T[p][orbit_of(tz, ty, 0)] += v0;
                    T[p][orbit_of(tz, ty, 1)] += v1;
                    T[p][orbit_of(tz, ty, 2)] += v2;
                    T[p][orbit_of(tz, ty, 3)] += v3;
                    T[p][orbit_of(tz, ty, 4)] += v4;
                }
            }
        }
    }

    float U[3][3] = {};
#pragma unroll
    for (int j = 0; j < 3; j++)
#pragma unroll
    for (int g = 0; g < 10; g++) {
        float bv = sB[j*10 + g];
        U[0][j] = fmaf(bv, T[0][g], U[0][j]);
        U[1][j] = fmaf(bv, T[1][g], U[1][j]);
        U[2][j] = fmaf(bv, T[2][g], U[2][j]);
    }

    const float4* w4 = (const float4*)sW;
    float* gout = out + (long)b * 20 * PLANE;
#pragma unroll
    for (int p = 0; p < 3; p++) {
        const int oz = oz0 + 3*zg + p;
        if (oz > 32) continue;
        float y[24];
#pragma unroll
        for (int c = 0; c < 24; c++) y[c] = 0.f;
#pragma unroll
        for (int j = 0; j < 3; j++)
#pragma unroll
        for (int q = 0; q < 6; q++) {
            float4 w = w4[j*6 + q];
            y[q*4+0] = fmaf(U[p][j], w.x, y[q*4+0]);
            y[q*4+1] = fmaf(U[p][j], w.y, y[q*4+1]);
            y[q*4+2] = fmaf(U[p][j], w.z, y[q*4+2]);
            y[q*4+3] = fmaf(U[p][j], w.w, y[q*4+3]);
        }
        float g0 = 1.f/(1.f + expf(-y[20]));
        float g1 = 1.f/(1.f + expf(-y[21]));
        float g2 = 1.f/(1.f + expf(-y[22]));
#pragma unroll
        for (int oc = 0; oc < 20; oc++) {
            float v = (oc < 5) ? fmaxf(y[oc], 0.f)
                               : y[oc] * (oc < 8 ? g0 : (oc < 13 ? g1 : g2));
            gout[((long)oc*PZ + (oz+3))*(PZ*PX) + (oy0+oy+3)*PX + (ox+3)] = v;
        }
    }
}

// ---------------------------------------------------------------------------
// conv1: CIN=20, act0 [39,39,40] -> 18^3. Tile (6z,6y,18x), 648 threads,
// 1 z-output/thread. Double-buffered contiguous 16B cp.async (smem layout ==
// global layout: 15 slabs of 15 rows x 40).
// ---------------------------------------------------------------------------
__global__ void __launch_bounds__(648, 1)
conv1_kernel(const float* __restrict__ in, const float* __restrict__ W,
             float* __restrict__ out, BC Bc)
{
    constexpr int NT = 648, SLAB = 600;
    extern __shared__ float dsm[];
    float* buf[2] = { dsm, dsm + 9000 };
    float* sW = dsm + 18000;                  // 1440, 16B-aligned
    float* sB = sW + 1440;                    // 30

    const int tid = threadIdx.x;
    const int b   = blockIdx.y;
    const int zt  = blockIdx.x / 3, yt = blockIdx.x % 3;
    const int oz0 = 6*zt, oy0 = 6*yt;

    for (int idx = tid; idx < 1440; idx += NT) {
        int ci = idx / 72, r = idx % 72, j = r / 24, o = r % 24;
        sW[idx] = (o < 23) ? W[(o*20 + ci)*3 + j] : 0.f;
    }
    if (tid < 30) sB[tid] = Bc.b[tid];

    const int ox  = tid % 18;
    const int r0  = tid / 18;
    const int oy  = r0 % 6;
    const int ozl = r0 / 6;        // 0..5

    float acc[24];
#pragma unroll
    for (int c = 0; c < 24; c++) acc[c] = 0.f;

    // 15 slabs; each: 15 y-rows x 40 = 600 contiguous floats in BOTH layouts
    auto issue = [&](int ci, float* dst) {
        const float* g = in + (long)(b*20 + ci)*PLANE
                            + (2*oz0)*(PZ*PX) + (2*oy0)*PX;
        for (int idx = tid; idx < 2250; idx += NT) {      // 15*150 16B-ops
            int iz = idx / 150, k = idx % 150;
            cp_async16(dst + iz*SLAB + 4*k, g + iz*(PZ*PX) + 4*k);
        }
        asm volatile("cp.async.commit_group;");
    };

    issue(0, buf[0]);
    for (int ci = 0; ci < 20; ci++) {
        float* cur = buf[ci & 1];
        if (ci + 1 < 20) {
            issue(ci + 1, buf[(ci + 1) & 1]);
            asm volatile("cp.async.wait_group 1;");
        } else {
            asm volatile("cp.async.wait_group 0;");
        }
        __syncthreads();

        float T[10];
#pragma unroll
        for (int g = 0; g < 10; g++) T[g] = 0.f;

#pragma unroll
        for (int tz = 0; tz < 5; tz++) {
#pragma unroll
            for (int ty = 0; ty < 5; ty++) {
                const float2* rp = (const float2*)
                    &cur[(2*ozl + tz)*SLAB + (2*oy + ty)*PX + 2*ox];
                float2 c0 = rp[0], c1 = rp[1], c2 = rp[2];
                T[orbit_of(tz, ty, 0)] += c0.x;
                T[orbit_of(tz, ty, 1)] += c0.y;
                T[orbit_of(tz, ty, 2)] += c1.x;
                T[orbit_of(tz, ty, 3)] += c1.y;
                T[orbit_of(tz, ty, 4)] += c2.x;
            }
        }

        float U[3] = {};
#pragma unroll
        for (int j = 0; j < 3; j++)
#pragma unroll
        for (int g = 0; g < 10; g++)
            U[j] = fmaf(sB[j*10 + g], T[g], U[j]);

        const float4* w4 = (const float4*)&sW[ci*72];
#pragma unroll
        for (int j = 0; j < 3; j++)
#pragma unroll
        for (int q = 0; q < 6; q++) {
            float4 w = w4[j*6 + q];
            acc[q*4+0] = fmaf(U[j], w.x, acc[q*4+0]);
            acc[q*4+1] = fmaf(U[j], w.y, acc[q*4+1]);
            acc[q*4+2] = fmaf(U[j], w.z, acc[q*4+2]);
            acc[q*4+3] = fmaf(U[j], w.w, acc[q*4+3]);
        }
        __syncthreads();   // protect buffer reuse
    }

    float* gout = out + (long)b * 20 * 5832;
    const int oz = oz0 + ozl;
    float g0 = 1.f/(1.f + expf(-acc[20]));
    float g1 = 1.f/(1.f + expf(-acc[21]));
    float g2 = 1.f/(1.f + expf(-acc[22]));
#pragma unroll
    for (int oc = 0; oc < 20; oc++) {
        float y = acc[oc];
        float v = (oc < 5) ? fmaxf(y, 0.f)
                           : y * (oc < 8 ? g0 : (oc < 13 ? g1 : g2));
        gout[((long)oc*18 + oz)*324 + (oy0 + oy)*18 + ox] = v;
    }
}

// ---------------------------------------------------------------------------
// kS + fused B-contraction: V[b,ci,j] = sum_t B[j,orbit(t)] * S_t
// ---------------------------------------------------------------------------
__global__ void kS_kernel(const float* __restrict__ act, float* __restrict__ V,
                          BC Bc) {
    __shared__ float s[5832];
    __shared__ float R[1620];     // [z][y][tx]
    __shared__ float sS[128];
    int ci = blockIdx.x;
    int b  = blockIdx.y;
    int tid = threadIdx.x;        // 128
    const float* p = act + (long)(b*20 + ci) * 5832;
    for (int i = tid; i < 5832; i += 128) s[i] = p[i];
    __syncthreads();

    for (int idx = tid; idx < 1620; idx += 128) {
        int z = idx / 90, r = idx % 90, y = r / 5, tx = r % 5;
        int lo = (3 - tx + 1) >> 1; if (lo < 0) lo = 0;
        int hi = (20 - tx) >> 1;    if (hi > 9) hi = 9;
        float sum = 0.f;
        const float* row = &s[(z*18 + y)*18];
        for (int oxx = lo; oxx <= hi; oxx++) sum += row[2*oxx + tx - 3];
        R[idx] = sum;
    }
    __syncthreads();

    if (tid < 125) {
        int tz = tid / 25, ty = (tid / 5) % 5, tx = tid % 5;
        int loz = (3 - tz + 1) >> 1; if (loz < 0) loz = 0;
        int hiz = (20 - tz) >> 1;    if (hiz > 9) hiz = 9;
        int loy = (3 - ty + 1) >> 1; if (loy < 0) loy = 0;
        int hiy = (20 - ty) >> 1;    if (hiy > 9) hiy = 9;
        float sum = 0.f;
        for (int oz = loz; oz <= hiz; oz++) {
            int z = 2*oz + tz - 3;
            for (int oyy = loy; oyy <= hiy; oyy++)
                sum += R[((z)*18 + (2*oyy + ty - 3))*5 + tx];
        }
        sS[tid] = sum;
    }
    __syncthreads();

    if (tid < 3) {
        float a = 0.f;
        for (int t = 0; t < 125; t++) {
            int tz = t / 25, ty = (t / 5) % 5, tx = t % 5;
            a = fmaf(Bc.b[tid*10 + orbit_of(tz, ty, tx)], sS[t], a);
        }
        V[(b*20 + ci)*3 + tid] = a;
    }
}

// ---------------------------------------------------------------------------
// head: one block per batch element (16 blocks x 64 threads).
// ---------------------------------------------------------------------------
__global__ void head_kernel(const float* __restrict__ V, const float* __restrict__ W2,
                            const float* __restrict__ fc1w, const float* __restrict__ fc1b,
                            const float* __restrict__ fc2w, const float* __restrict__ fc2b,
                            float* __restrict__ out)
{
    __shared__ float sV[60];
    __shared__ float sW2[1380];
    __shared__ float sF1[1000];
    __shared__ float pooled[20];
    __shared__ float h1[50];
    const int b = blockIdx.x;
    const int t = threadIdx.x;     // 64
    if (t < 60) sV[t] = V[b*60 + t];
    for (int i = t; i < 1380; i += 64) sW2[i] = W2[i];
    for (int i = t; i < 1000; i += 64) sF1[i] = fc1w[i];
    __syncthreads();
    if (t < 20) {
        float a = 0.f;
        for (int k = 0; k < 60; k++)
            a = fmaf(sW2[t*60 + k], sV[k], a);
        pooled[t] = a * (1.0f/1000.0f);
    }
    __syncthreads();
    if (t < 50) {
        float a = fc1b[t];
        for (int k = 0; k < 20; k++)
            a = fmaf(pooled[k], sF1[t*20 + k], a);
        h1[t] = fmaxf(a, 0.f);
    }
    __syncthreads();
    if (t < 2) {
        float a = fc2b[t];
        for (int k = 0; k < 50; k++)
            a = fmaf(h1[k], fc2w[t*50 + k], a);
        out[b*2 + t] = a;
    }
}

// ---------------------------------------------------------------------------
extern "C" void kernel_launch(void* const* d_in, const int* in_sizes, int n_in,
                              void* d_out, int out_size) {
    const float* inp  = (const float*)d_in[0];
    const float* W0   = (const float*)d_in[1];
    const float* W1   = (const float*)d_in[2];
    const float* W2   = (const float*)d_in[3];
    const float* fc1w = (const float*)d_in[4];
    const float* fc1b = (const float*)d_in[5];
    const float* fc2w = (const float*)d_in[6];
    const float* fc2b = (const float*)d_in[7];
    float* out = (float*)d_out;

    BC bc;
    {
        const double r2s[10]  = {0,1,2,3,4,5,6,8,9,12};
        const double mult[10] = {1,6,12,8,6,24,24,12,24,8};
        for (int j = 0; j < 3; j++) {
            double v[10], sm = 0.0;
            for (int g = 0; g < 10; g++) {
                double d = (sqrt(r2s[g]) - (double)j) / 0.6;
                v[g] = exp(-0.5 * d * d);
                sm += mult[g] * v[g] * v[g];
            }
            double inv = 1.0 / sqrt(sm);
            for (int g = 0; g < 10; g++) bc.b[j*10 + g] = (float)(v[g] * inv);
        }
    }

    float *gA0, *gA1, *gV;
    cudaGetSymbolAddress((void**)&gA0, g_act0);
    cudaGetSymbolAddress((void**)&gA1, g_act1);
    cudaGetSymbolAddress((void**)&gV,  g_V);

    constexpr int SMEM0 = (13232 + 72 + 32) * 4;        // 53.3 KB
    cudaFuncSetAttribute(conv0_kernel,
                         cudaFuncAttributeMaxDynamicSharedMemorySize, SMEM0);
    conv0_kernel<<<dim3(4*11, 16), 297, SMEM0>>>(inp, W0, gA0, bc);

    constexpr int SMEM1 = (18000 + 1440 + 32) * 4;      // 77.9 KB
    cudaFuncSetAttribute(conv1_kernel,
                         cudaFuncAttributeMaxDynamicSharedMemorySize, SMEM1);
    conv1_kernel<<<dim3(3*3, 16), 648, SMEM1>>>(gA0, W1, gA1, bc);

    kS_kernel<<<dim3(20, 16), 128>>>(gA1, gV, bc);
    head_kernel<<<16, 64>>>(gV, W2, fc1w, fc1b, fc2w, fc2b, out);
}